// round 10
// baseline (speedup 1.0000x reference)
#include <cuda_runtime.h>
#include <cstdint>

// VecArrayMultiplier54x54: the {0,1} gate network is exact, so
// out[row] = bits of (uint54(A[row]) * uint54(B[row])), LSB first, as 0/1 floats.
//
// R10 = R9 (2048 warps, 4 rows/warp, 16 front-batched LDG.32, guard-free,
// constant offsets) with BLOCKED row mapping: warp w -> rows 4w..4w+3.
// Each warp's A/B inputs become one contiguous 864B span (~7 L2 lines vs ~12
// strided) and its output one contiguous 1728B span; row-boundary lines are
// reused within the warp via L1 instead of being fetched by two warps.
// Epilogue per row: 4 ballots -> 64x64->128 IMAD -> lane<27 STG.128 of
// bit-pattern floats (bit * 0x3F800000, no I2F).

#define ROWS_PER_WARP 4

__global__ void __launch_bounds__(256)
mul54x54_r10_kernel(const float* __restrict__ A,
                    const float* __restrict__ B,
                    float* __restrict__ out) {
    const int gwarp = (int)((blockIdx.x * blockDim.x + threadIdx.x) >> 5);
    const int lane  = threadIdx.x & 31;

    // Blocked: warp covers rows [4*gwarp, 4*gwarp+4): contiguous 864B per operand.
    const float* __restrict__ a0 = A + (size_t)gwarp * (ROWS_PER_WARP * 54);
    const float* __restrict__ b0 = B + (size_t)gwarp * (ROWS_PER_WARP * 54);

    float av0[ROWS_PER_WARP], bv0[ROWS_PER_WARP];
    float av1[ROWS_PER_WARP], bv1[ROWS_PER_WARP];

    const bool tail = (lane < 22);

    // 16 independent LDG.32, small constant offsets (i*216B) -> immediate form.
    #pragma unroll
    for (int i = 0; i < ROWS_PER_WARP; i++) {
        const int off = i * 54;
        av0[i] = a0[off + lane];
        bv0[i] = b0[off + lane];
        av1[i] = 0.0f; bv1[i] = 0.0f;
        if (tail) {
            av1[i] = a0[off + 32 + lane];
            bv1[i] = b0[off + 32 + lane];
        }
    }

    // Output: contiguous 1728B region for the 4 rows.
    uint4* __restrict__ o = (uint4*)(out + (size_t)gwarp * (ROWS_PER_WARP * 108));

    #pragma unroll
    for (int i = 0; i < ROWS_PER_WARP; i++) {
        unsigned ma0 = __ballot_sync(0xFFFFFFFFu, av0[i] > 0.5f);
        unsigned ma1 = __ballot_sync(0xFFFFFFFFu, av1[i] > 0.5f);
        unsigned mb0 = __ballot_sync(0xFFFFFFFFu, bv0[i] > 0.5f);
        unsigned mb1 = __ballot_sync(0xFFFFFFFFu, bv1[i] > 0.5f);

        const uint64_t a = (uint64_t)ma0 | ((uint64_t)(ma1 & 0x3FFFFFu) << 32);
        const uint64_t b = (uint64_t)mb0 | ((uint64_t)(mb1 & 0x3FFFFFu) << 32);

        const uint64_t lo = a * b;             // product bits [0:64)
        const uint64_t hi = __umul64hi(a, b);  // product bits [64:108)

        if (lane < 27) {
            unsigned nib = (lane < 16) ? (unsigned)(lo >> (lane * 4))
                                       : (unsigned)(hi >> ((lane - 16) * 4));
            uint4 v;
            v.x = ( nib        & 1u) * 0x3F800000u;
            v.y = ((nib >> 1)  & 1u) * 0x3F800000u;
            v.z = ((nib >> 2)  & 1u) * 0x3F800000u;
            v.w = ((nib >> 3)  & 1u) * 0x3F800000u;
            o[i * 27 + lane] = v;
        }
    }
}

// Generic fallback for unexpected batch sizes (1 row/warp, guarded).
__global__ void __launch_bounds__(256)
mul54x54_generic_kernel(const float* __restrict__ A,
                        const float* __restrict__ B,
                        float* __restrict__ out,
                        int batch) {
    const int row  = (int)((blockIdx.x * blockDim.x + threadIdx.x) >> 5);
    const int lane = threadIdx.x & 31;
    if (row >= batch) return;

    const float* __restrict__ a_row = A + (size_t)row * 54;
    const float* __restrict__ b_row = B + (size_t)row * 54;

    float av0 = a_row[lane], bv0 = b_row[lane];
    float av1 = 0.0f, bv1 = 0.0f;
    if (lane < 22) { av1 = a_row[32 + lane]; bv1 = b_row[32 + lane]; }

    unsigned ma0 = __ballot_sync(0xFFFFFFFFu, av0 > 0.5f);
    unsigned ma1 = __ballot_sync(0xFFFFFFFFu, av1 > 0.5f);
    unsigned mb0 = __ballot_sync(0xFFFFFFFFu, bv0 > 0.5f);
    unsigned mb1 = __ballot_sync(0xFFFFFFFFu, bv1 > 0.5f);

    const uint64_t a = (uint64_t)ma0 | ((uint64_t)(ma1 & 0x3FFFFFu) << 32);
    const uint64_t b = (uint64_t)mb0 | ((uint64_t)(mb1 & 0x3FFFFFu) << 32);
    const uint64_t lo = a * b;
    const uint64_t hi = __umul64hi(a, b);

    if (lane < 27) {
        unsigned nib = (lane < 16) ? (unsigned)(lo >> (lane * 4))
                                   : (unsigned)(hi >> ((lane - 16) * 4));
        uint4 v;
        v.x = ( nib        & 1u) * 0x3F800000u;
        v.y = ((nib >> 1)  & 1u) * 0x3F800000u;
        v.z = ((nib >> 2)  & 1u) * 0x3F800000u;
        v.w = ((nib >> 3)  & 1u) * 0x3F800000u;
        ((uint4*)(out + (size_t)row * 108))[lane] = v;
    }
}

extern "C" void kernel_launch(void* const* d_in, const int* in_sizes, int n_in,
                              void* d_out, int out_size) {
    const float* A = (const float*)d_in[0];
    const float* B = (const float*)d_in[1];
    float* out = (float*)d_out;

    const int batch = in_sizes[0] / 54;     // 8192 expected
    constexpr int NWARPS = 2048;            // 256 CTAs x 256 threads

    if (batch == NWARPS * ROWS_PER_WARP) {
        mul54x54_r10_kernel<<<256, 256>>>(A, B, out);
    } else {
        const int blocks = (batch + 7) / 8; // 1 row/warp fallback
        mul54x54_generic_kernel<<<blocks, 256>>>(A, B, out, batch);
    }
}

// round 11
// speedup vs baseline: 1.0048x; 1.0048x over previous
#include <cuda_runtime.h>
#include <cstdint>

// VecArrayMultiplier54x54: the {0,1} gate network is exact, so
// out[row] = bits of (uint54(A[row]) * uint54(B[row])), LSB first, as 0/1 floats.
//
// R11 = converged dataflow (2048 warps, 4 rows/warp blocked, 16 front-batched
// LDG.32 with constant immediate offsets, guard-free, bit-pattern STG.128
// epilogue) at the last untested geometry: 128 CTAs x 512 threads.
// <1 CTA/SM -> minimal dispatch + no cross-CTA L1tex queue contention.

#define ROWS_PER_WARP 4

__global__ void __launch_bounds__(512)
mul54x54_r11_kernel(const float* __restrict__ A,
                    const float* __restrict__ B,
                    float* __restrict__ out) {
    const int gwarp = (int)((blockIdx.x * blockDim.x + threadIdx.x) >> 5);
    const int lane  = threadIdx.x & 31;

    // Blocked: warp covers rows [4*gwarp, 4*gwarp+4): contiguous 864B per operand.
    const float* __restrict__ a0 = A + (size_t)gwarp * (ROWS_PER_WARP * 54);
    const float* __restrict__ b0 = B + (size_t)gwarp * (ROWS_PER_WARP * 54);

    float av0[ROWS_PER_WARP], bv0[ROWS_PER_WARP];
    float av1[ROWS_PER_WARP], bv1[ROWS_PER_WARP];

    const bool tail = (lane < 22);

    // 16 independent LDG.32, small constant offsets (i*216B) -> immediate form.
    #pragma unroll
    for (int i = 0; i < ROWS_PER_WARP; i++) {
        const int off = i * 54;
        av0[i] = a0[off + lane];
        bv0[i] = b0[off + lane];
        av1[i] = 0.0f; bv1[i] = 0.0f;
        if (tail) {
            av1[i] = a0[off + 32 + lane];
            bv1[i] = b0[off + 32 + lane];
        }
    }

    // Output: contiguous 1728B region for the 4 rows.
    uint4* __restrict__ o = (uint4*)(out + (size_t)gwarp * (ROWS_PER_WARP * 108));

    #pragma unroll
    for (int i = 0; i < ROWS_PER_WARP; i++) {
        unsigned ma0 = __ballot_sync(0xFFFFFFFFu, av0[i] > 0.5f);
        unsigned ma1 = __ballot_sync(0xFFFFFFFFu, av1[i] > 0.5f);
        unsigned mb0 = __ballot_sync(0xFFFFFFFFu, bv0[i] > 0.5f);
        unsigned mb1 = __ballot_sync(0xFFFFFFFFu, bv1[i] > 0.5f);

        const uint64_t a = (uint64_t)ma0 | ((uint64_t)(ma1 & 0x3FFFFFu) << 32);
        const uint64_t b = (uint64_t)mb0 | ((uint64_t)(mb1 & 0x3FFFFFu) << 32);

        const uint64_t lo = a * b;             // product bits [0:64)
        const uint64_t hi = __umul64hi(a, b);  // product bits [64:108)

        if (lane < 27) {
            unsigned nib = (lane < 16) ? (unsigned)(lo >> (lane * 4))
                                       : (unsigned)(hi >> ((lane - 16) * 4));
            uint4 v;
            v.x = ( nib        & 1u) * 0x3F800000u;
            v.y = ((nib >> 1)  & 1u) * 0x3F800000u;
            v.z = ((nib >> 2)  & 1u) * 0x3F800000u;
            v.w = ((nib >> 3)  & 1u) * 0x3F800000u;
            o[i * 27 + lane] = v;
        }
    }
}

// Generic fallback for unexpected batch sizes (1 row/warp, guarded).
__global__ void __launch_bounds__(256)
mul54x54_generic_kernel(const float* __restrict__ A,
                        const float* __restrict__ B,
                        float* __restrict__ out,
                        int batch) {
    const int row  = (int)((blockIdx.x * blockDim.x + threadIdx.x) >> 5);
    const int lane = threadIdx.x & 31;
    if (row >= batch) return;

    const float* __restrict__ a_row = A + (size_t)row * 54;
    const float* __restrict__ b_row = B + (size_t)row * 54;

    float av0 = a_row[lane], bv0 = b_row[lane];
    float av1 = 0.0f, bv1 = 0.0f;
    if (lane < 22) { av1 = a_row[32 + lane]; bv1 = b_row[32 + lane]; }

    unsigned ma0 = __ballot_sync(0xFFFFFFFFu, av0 > 0.5f);
    unsigned ma1 = __ballot_sync(0xFFFFFFFFu, av1 > 0.5f);
    unsigned mb0 = __ballot_sync(0xFFFFFFFFu, bv0 > 0.5f);
    unsigned mb1 = __ballot_sync(0xFFFFFFFFu, bv1 > 0.5f);

    const uint64_t a = (uint64_t)ma0 | ((uint64_t)(ma1 & 0x3FFFFFu) << 32);
    const uint64_t b = (uint64_t)mb0 | ((uint64_t)(mb1 & 0x3FFFFFu) << 32);
    const uint64_t lo = a * b;
    const uint64_t hi = __umul64hi(a, b);

    if (lane < 27) {
        unsigned nib = (lane < 16) ? (unsigned)(lo >> (lane * 4))
                                   : (unsigned)(hi >> ((lane - 16) * 4));
        uint4 v;
        v.x = ( nib        & 1u) * 0x3F800000u;
        v.y = ((nib >> 1)  & 1u) * 0x3F800000u;
        v.z = ((nib >> 2)  & 1u) * 0x3F800000u;
        v.w = ((nib >> 3)  & 1u) * 0x3F800000u;
        ((uint4*)(out + (size_t)row * 108))[lane] = v;
    }
}

extern "C" void kernel_launch(void* const* d_in, const int* in_sizes, int n_in,
                              void* d_out, int out_size) {
    const float* A = (const float*)d_in[0];
    const float* B = (const float*)d_in[1];
    float* out = (float*)d_out;

    const int batch = in_sizes[0] / 54;     // 8192 expected
    constexpr int NWARPS = 2048;            // 128 CTAs x 512 threads

    if (batch == NWARPS * ROWS_PER_WARP) {
        mul54x54_r11_kernel<<<128, 512>>>(A, B, out);
    } else {
        const int blocks = (batch + 7) / 8; // 1 row/warp fallback
        mul54x54_generic_kernel<<<blocks, 256>>>(A, B, out, batch);
    }
}